// round 14
// baseline (speedup 1.0000x reference)
#include <cuda_runtime.h>
#include <math.h>

#define BB 16
#define NN 128
#define DD 64
#define BN  2048        // BB*NN
#define BND 131072      // BN*DD
#define BNDD 8388608    // BND*DD

// out layout: prediction[BND], target[BND], A_new[BN*NN], W1n[BNDD], W2n[BNDD], W3n[BNDD]
#define OFF_T  (BND)
#define OFF_A  (2*BND)
#define OFF_W1 (4*BND)            // 2*BND + BN*NN = 4*BND
#define OFF_W2 (OFF_W1 + BNDD)
#define OFF_W3 (OFF_W2 + BNDD)

// k2 tiled smem layout (floats): Ks[128][65], Os[128][65], anew[8][128], wq[8][64]
#define K2_LDK   65
#define K2_OFF_OS   (NN * K2_LDK)
#define K2_OFF_AN   (2 * NN * K2_LDK)
#define K2_OFF_WQ   (K2_OFF_AN + 8 * NN)
#define K2_SMEM_FLOATS (K2_OFF_WQ + 8 * DD)
#define K2_SMEM_BYTES  (K2_SMEM_FLOATS * 4)

// scratch (static device globals; no allocation)
__device__ float g_q[BND];
__device__ float g_k[BND];
__device__ float g_coef[BND];
__device__ float g_noisy[BND];
__device__ float g_pbn_m[BN];
__device__ float g_pbn_e[BN];
__device__ float g_pbn_e2[BN];
__device__ float g_mag[BB];
__device__ float g_gmask[DD];
__device__ float g_std;
__device__ unsigned g_cnt = 0;

__device__ __forceinline__ float wredMax(float v) {
    #pragma unroll
    for (int o = 16; o; o >>= 1) v = fmaxf(v, __shfl_xor_sync(0xffffffffu, v, o));
    return v;
}
__device__ __forceinline__ float wredSum(float v) {
    #pragma unroll
    for (int o = 16; o; o >>= 1) v += __shfl_xor_sync(0xffffffffu, v, o);
    return v;
}

// ---------------------------------------------------------------------------
// K1: per (b,n) three matvecs (pred/k/q). 1 bn per 96-thread block with
// j-loop split in half -> grid 2048, single wave. (proven R12 version)
// ---------------------------------------------------------------------------
__global__ void __launch_bounds__(96, 14) k1_qkp(
    const float* __restrict__ state,
    const float* __restrict__ W1, const float* __restrict__ W2, const float* __restrict__ W3,
    float* __restrict__ out)
{
    int t   = threadIdx.x;
    int jh  = t / 48;         // 0..1 : j-half
    int r   = t % 48;
    int x   = r >> 4;         // 0: W1(pred), 1: W2(k), 2: W3(q)
    int kk  = r & 15;         // float4 column group
    int bn  = blockIdx.x;

    __shared__ float  s[DD];
    __shared__ float4 part[2][48];

    if (t < DD) s[t] = state[bn * DD + t];
    __syncthreads();

    const float* Wp = (x == 0) ? W1 : ((x == 1) ? W2 : W3);
    const float4* Wb = (const float4*)(Wp + (size_t)bn * DD * DD) + kk;

    float4 acc = {0.f, 0.f, 0.f, 0.f};
    int j0 = jh * 32;
    #pragma unroll 8
    for (int j = j0; j < j0 + 32; j++) {
        float  sv = s[j];
        float4 w  = Wb[j * 16];
        acc.x += sv * w.x; acc.y += sv * w.y;
        acc.z += sv * w.z; acc.w += sv * w.w;
    }
    part[jh][r] = acc;
    __syncthreads();

    if (t < 48) {
        float4 a = part[0][r];
        float4 bq = part[1][r];
        float4 acc2 = { a.x + bq.x, a.y + bq.y, a.z + bq.z, a.w + bq.w };

        if (x == 0) {
            const float C = 1.8477590650225735f;  // sqrt(2+sqrt(2))
            float4 p;
            p.x = tanhf(acc2.x - tanhf(acc2.x) * 0.6f) * C;
            p.y = tanhf(acc2.y - tanhf(acc2.y) * 0.6f) * C;
            p.z = tanhf(acc2.z - tanhf(acc2.z) * 0.6f) * C;
            p.w = tanhf(acc2.w - tanhf(acc2.w) * 0.6f) * C;
            ((float4*)out)[bn * 16 + kk] = p;
        } else if (x == 1) {
            ((float4*)g_k)[bn * 16 + kk] = acc2;
        } else {
            ((float4*)g_q)[bn * 16 + kk] = acc2;
        }
    }
}

// ---------------------------------------------------------------------------
// K2 TILED: 256 blocks x 256 threads (8 warps). Block = (b, 8 attention
// rows) -> all 148 SMs engaged (vs 128 blocks before). K/output staged once
// per block; warp per row, softmax warp-local. Per-warp math identical to
// the 16-row version (bit-exact outputs). Fused stats via last-block-done.
// ---------------------------------------------------------------------------
__global__ void __launch_bounds__(256) k2_attn(
    const float* __restrict__ A,
    const float* __restrict__ noiseA,
    const float* __restrict__ outputv,
    const float* __restrict__ eye,
    const float* __restrict__ stomach,
    const float* __restrict__ state,
    const int* __restrict__ stepc,
    float* __restrict__ out)
{
    extern __shared__ float dsm[];
    float* Ks  = dsm;                 // [128][65]
    float* Os  = dsm + K2_OFF_OS;     // [128][65]
    float* ans = dsm + K2_OFF_AN;     // [8][128]
    float* wq  = dsm + K2_OFF_WQ;     // [8][64]

    int t  = threadIdx.x;
    int w  = t >> 5;                  // warp 0..7 = row within tile
    int l  = t & 31;
    int b  = blockIdx.x >> 4;
    int n  = (blockIdx.x & 15) * 8 + w;
    int bn = b * NN + n;

    // stage K and output slices of batch b
    {
        const float4* gk = (const float4*)(g_k + (size_t)b * NN * DD);
        const float4* go = (const float4*)(outputv + (size_t)b * NN * DD);
        for (int i = t; i < NN * DD / 4; i += 256) {
            int row = i >> 4;
            int c4  = (i & 15) * 4;
            float4 kv = gk[i];
            float4 ov = go[i];
            float* kd = Ks + row * K2_LDK + c4;
            kd[0] = kv.x; kd[1] = kv.y; kd[2] = kv.z; kd[3] = kv.w;
            float* od = Os + row * K2_LDK + c4;
            od[0] = ov.x; od[1] = ov.y; od[2] = ov.z; od[3] = ov.w;
        }
        if (l < 16) {
            float4 qv = ((const float4*)(g_q + (size_t)bn * DD))[l];
            float* qd = wq + w * DD + l * 4;
            qd[0] = qv.x; qd[1] = qv.y; qd[2] = qv.z; qd[3] = qv.w;
        }
    }
    __syncthreads();

    float ae = 0.f, ae2 = 0.f, am = 0.f;

    if (n < 2) {
        #pragma unroll
        for (int r = 0; r < 4; r++)
            out[OFF_A + (size_t)bn * NN + l + 32 * r] = 0.f;
        const float* env = (n == 0) ? (eye + b * DD) : (stomach + b * DD);
        #pragma unroll
        for (int r = 0; r < 2; r++) {
            int col = l + 32 * r;
            float tv = env[col];
            out[OFF_T + bn * DD + col] = tv;
            float err = out[bn * DD + col] - tv;
            ae += err; ae2 += err * err;
            am += fabsf(state[bn * DD + col]);
        }
    } else {
        float raw[4];
        const float* qv = wq + w * DD;
        #pragma unroll
        for (int r = 0; r < 4; r++) {
            int m = l + 32 * r;
            const float* kr = Ks + m * K2_LDK;
            float dot = 0.f;
            #pragma unroll 8
            for (int j = 0; j < DD; j++) dot += qv[j] * kr[j];
            raw[r] = dot * 0.125f + noiseA[(size_t)bn * NN + m] * 1e-5f;
        }

        float mx = fmaxf(fmaxf(raw[0], raw[1]), fmaxf(raw[2], raw[3]));
        mx = wredMax(mx);

        float e[4], ls = 0.f;
        #pragma unroll
        for (int r = 0; r < 4; r++) { e[r] = expf(raw[r] - mx); ls += e[r]; }
        float sum = wredSum(ls);

        float maxpd = 1.0f / sum;      // max element has e == 1.0f exactly
        float lek = 0.f;
        float ek[4];
        #pragma unroll
        for (int r = 0; r < 4; r++) {
            float pd = e[r] / sum;
            bool keep = (pd > (1.0f / 129.0f)) || (pd == maxpd);
            ek[r] = keep ? e[r] : 0.f;
            lek += ek[r];
        }
        float sum2 = wredSum(lek);

        #pragma unroll
        for (int r = 0; r < 4; r++) {
            int m = l + 32 * r;
            float P  = ek[r] / sum2;
            float an = A[(size_t)bn * NN + m] * 0.99f + P * 0.01f;
            out[OFF_A + (size_t)bn * NN + m] = an;
            ans[w * NN + m] = an;
        }
        __syncwarp();

        const float* aw = ans + w * NN;
        #pragma unroll
        for (int r = 0; r < 2; r++) {
            int col = l + 32 * r;
            float acc = 0.f;
            #pragma unroll 8
            for (int m = 0; m < NN; m++)
                acc += aw[m] * Os[m * K2_LDK + col];
            out[OFF_T + bn * DD + col] = acc;
            float err = out[bn * DD + col] - acc;
            ae += err; ae2 += err * err;
            am += fabsf(state[bn * DD + col]);
        }
    }

    // per-bn stats: pure warp reduce, lane 0 writes
    ae  = wredSum(ae);
    ae2 = wredSum(ae2);
    am  = wredSum(am);
    if (l == 0) {
        g_pbn_e[bn]  = ae;
        g_pbn_e2[bn] = ae2;
        g_pbn_m[bn]  = am;
    }

    // last-block final reduction
    __shared__ int isLast;
    __syncthreads();
    if (t == 0) {
        __threadfence();
        unsigned old = atomicAdd(&g_cnt, 1u);
        isLast = (old == 255u) ? 1 : 0;
    }
    __syncthreads();
    if (isLast) {
        // per-b mag: 8 lanes per b, each sums 16 entries
        if (t < 128) {
            int bb = t >> 3, j = t & 7;
            float s = 0.f;
            int base = bb * NN + j * 16;
            #pragma unroll
            for (int i = 0; i < 16; i++) s += g_pbn_m[base + i];
            #pragma unroll
            for (int o = 4; o; o >>= 1) s += __shfl_xor_sync(0xffffffffu, s, o);
            if (j == 0) g_mag[bb] = s;
        }
        // global err sums over 2048 partials with all 256 threads
        {
            float e = 0.f, e2 = 0.f;
            for (int i = t; i < BN; i += 256) { e += g_pbn_e[i]; e2 += g_pbn_e2[i]; }
            e = wredSum(e); e2 = wredSum(e2);
            __shared__ float r0[8], r1[8];
            if (l == 0) { r0[w] = e; r1[w] = e2; }
            __syncthreads();
            if (t == 0) {
                float E = 0.f, E2 = 0.f;
                #pragma unroll
                for (int i = 0; i < 8; i++) { E += r0[i]; E2 += r1[i]; }
                const float M = (float)BND;
                float var = (E2 - E * E / M) / (M - 1.0f);
                g_std = sqrtf(fmaxf(var, 0.f));
                g_cnt = 0u;   // reset for next graph replay
            }
        }
        // travelling gaussian column mask
        if (t < DD) {
            float scf    = (float)(*stepc) + 1.0f;
            float center = fmodf(scf * 0.5f, 64.0f);
            float d = fabsf((float)t - center);
            d = fminf(d, 64.f - d);
            g_gmask[t] = expf(-d * d / 0.020001f);
        }
    }
}

// ---------------------------------------------------------------------------
// K4: warp per (b,n): E_curr softmax over D, Eb EMA, plasticity/mask,
// noisy_state, outer-product rms factorization -> coef, noisy.
// ---------------------------------------------------------------------------
__global__ void __launch_bounds__(256) k4_coef(
    const float* __restrict__ state,
    const float* __restrict__ Ebase,
    const float* __restrict__ n1raw,
    const float* __restrict__ n2raw,
    const float* __restrict__ out)
{
    int bn   = blockIdx.x * 8 + (threadIdx.x >> 5);
    int lane = threadIdx.x & 31;
    int b    = bn >> 7;
    int g0   = bn * DD + lane;
    int g1   = g0 + 32;

    float errA = out[g0] - out[OFF_T + g0];
    float errB = out[g1] - out[OFF_T + g1];

    float mx = wredMax(fmaxf(errA, errB));
    float exA = expf(errA - mx), exB = expf(errB - mx);
    float sm = wredSum(exA + exB);
    float EcA = exA / sm, EcB = exB / sm;

    float Eb0A = Ebase[g0], Eb0B = Ebase[g1];
    float EbA = (Eb0A == 0.f) ? EcA : Eb0A;
    float EbB = (Eb0B == 0.f) ? EcB : Eb0B;
    EbA = EbA * 0.95f + 0.05f * EcA;
    EbB = EbB * 0.95f + 0.05f * EcB;
    float advA = EcA - EbA, advB = EcB - EbB;
    float plA = 1.f + advA * rsqrtf(advA * advA + 1e-6f);
    float plB = 1.f + advB * rsqrtf(advB * advB + 1e-6f);
    float mkA = (EbA > 0.f) ? 1.f : 0.f;
    float mkB = (EbB > 0.f) ? 1.f : 0.f;

    float inv_mag = 1.f / (1.f + g_mag[b]);
    float sd = g_std * 0.8f;
    float nsA = state[g0] + n1raw[g0] * inv_mag + n2raw[g0] * sd;
    float nsB = state[g1] + n1raw[g1] * inv_mag + n2raw[g1] * sd;

    float se2 = wredSum(errA * errA + errB * errB);
    float sn2 = wredSum(nsA * nsA + nsB * nsB);
    float rn = rsqrtf((se2 * (1.f / DD)) * (sn2 * (1.f / DD)) + 1e-6f);

    g_coef[g0]  = -errA * rn * plA * mkA;
    g_coef[g1]  = -errB * rn * plB * mkB;
    g_noisy[g0] = nsA;
    g_noisy[g1] = nsB;
}

// ---------------------------------------------------------------------------
// K5: fused grads + momentum + gaussian mask + W update + row rms.
// Reversed walk; __ldcs on M, __stcs on stores. min-blocks 8 = full
// occupancy (regs=32 fits exactly).
// ---------------------------------------------------------------------------
__device__ __forceinline__ float newW(float w, float wlat, float m, float h, float g) {
    float grad = h + 0.01f * wlat - 0.01f * w;     // LAT_DECAY*W_lat - WD*W_self
    return w + 0.0033f * (m * 0.4f + 0.6f * grad * g);
}

__global__ void __launch_bounds__(256, 8) k5_update(
    const float* __restrict__ W1, const float* __restrict__ W2, const float* __restrict__ W3,
    const float* __restrict__ M1, const float* __restrict__ M2, const float* __restrict__ M3,
    float* __restrict__ out)
{
    int t   = threadIdx.x;
    int tx  = t & 15;
    int blk = (int)gridDim.x - 1 - (int)blockIdx.x;   // reversed walk
    int row = blk * 16 + (t >> 4);         // 0..BND-1  (b,n,i)
    int bn  = row >> 6;
    size_t b4 = (size_t)row * 16 + tx;     // float4 index into (BND x D) matrices

    float4 w1 = ((const float4*)W1)[b4];
    float4 w2 = ((const float4*)W2)[b4];
    float4 w3 = ((const float4*)W3)[b4];

    float  c  = g_coef[row];
    float4 ns = ((const float4*)g_noisy)[bn * 16 + tx];
    float4 gm = ((const float4*)g_gmask)[tx];
    float4 h  = { c * ns.x, c * ns.y, c * ns.z, c * ns.w };

    // --- W1 update ---
    {
        float4 m1 = __ldcs(((const float4*)M1) + b4);
        float4 t1;
        t1.x = newW(w1.x, w3.x, m1.x, h.x, gm.x);
        t1.y = newW(w1.y, w3.y, m1.y, h.y, gm.y);
        t1.z = newW(w1.z, w3.z, m1.z, h.z, gm.z);
        t1.w = newW(w1.w, w3.w, m1.w, h.w, gm.w);
        float s1 = t1.x*t1.x + t1.y*t1.y + t1.z*t1.z + t1.w*t1.w;
        #pragma unroll
        for (int o = 8; o; o >>= 1) s1 += __shfl_xor_sync(0xffffffffu, s1, o);
        float r1 = rsqrtf(s1 * (1.f / 64.f) + 1e-6f);
        float4 o1 = { t1.x*r1, t1.y*r1, t1.z*r1, t1.w*r1 };
        __stcs(((float4*)(out + OFF_W1)) + b4, o1);
    }
    // --- W2 update ---
    {
        float4 m2 = __ldcs(((const float4*)M2) + b4);
        float4 t2;
        t2.x = newW(w2.x, w1.x, m2.x, h.x, gm.x);
        t2.y = newW(w2.y, w1.y, m2.y, h.y, gm.y);
        t2.z = newW(w2.z, w1.z, m2.z, h.z, gm.z);
        t2.w = newW(w2.w, w1.w, m2.w, h.w, gm.w);
        float s2 = t2.x*t2.x + t2.y*t2.y + t2.z*t2.z + t2.w*t2.w;
        #pragma unroll
        for (int o = 8; o; o >>= 1) s2 += __shfl_xor_sync(0xffffffffu, s2, o);
        float r2 = rsqrtf(s2 * (1.f / 64.f) + 1e-6f);
        float4 o2 = { t2.x*r2, t2.y*r2, t2.z*r2, t2.w*r2 };
        __stcs(((float4*)(out + OFF_W2)) + b4, o2);
    }
    // --- W3 update ---
    {
        float4 m3 = __ldcs(((const float4*)M3) + b4);
        float4 t3;
        t3.x = newW(w3.x, w2.x, m3.x, h.x, gm.x);
        t3.y = newW(w3.y, w2.y, m3.y, h.y, gm.y);
        t3.z = newW(w3.z, w2.z, m3.z, h.z, gm.z);
        t3.w = newW(w3.w, w2.w, m3.w, h.w, gm.w);
        float s3 = t3.x*t3.x + t3.y*t3.y + t3.z*t3.z + t3.w*t3.w;
        #pragma unroll
        for (int o = 8; o; o >>= 1) s3 += __shfl_xor_sync(0xffffffffu, s3, o);
        float r3 = rsqrtf(s3 * (1.f / 64.f) + 1e-6f);
        float4 o3 = { t3.x*r3, t3.y*r3, t3.z*r3, t3.w*r3 };
        __stcs(((float4*)(out + OFF_W3)) + b4, o3);
    }
}

// ---------------------------------------------------------------------------
extern "C" void kernel_launch(void* const* d_in, const int* in_sizes, int n_in,
                              void* d_out, int out_size)
{
    const float* eye     = (const float*)d_in[0];
    const float* stomach = (const float*)d_in[1];
    const float* state   = (const float*)d_in[2];
    const float* outputv = (const float*)d_in[3];
    const float* W1      = (const float*)d_in[4];
    const float* W2      = (const float*)d_in[5];
    const float* W3      = (const float*)d_in[6];
    const float* M1      = (const float*)d_in[7];
    const float* M2      = (const float*)d_in[8];
    const float* M3      = (const float*)d_in[9];
    const float* Ebase   = (const float*)d_in[10];
    const float* A       = (const float*)d_in[11];
    const float* noiseA  = (const float*)d_in[12];
    const float* n1raw   = (const float*)d_in[13];
    const float* n2raw   = (const float*)d_in[14];
    const int*   stepc   = (const int*)d_in[15];
    float* out = (float*)d_out;

    cudaFuncSetAttribute(k2_attn, cudaFuncAttributeMaxDynamicSharedMemorySize,
                         K2_SMEM_BYTES);

    k1_qkp<<<BN, 96>>>(state, W1, W2, W3, out);
    k2_attn<<<256, 256, K2_SMEM_BYTES>>>(A, noiseA, outputv, eye, stomach, state, stepc, out);
    k4_coef<<<BN / 8, 256>>>(state, Ebase, n1raw, n2raw, out);
    k5_update<<<BND / 16, 256>>>(W1, W2, W3, M1, M2, M3, out);
}

// round 15
// speedup vs baseline: 1.1866x; 1.1866x over previous
#include <cuda_runtime.h>
#include <math.h>

#define BB 16
#define NN 128
#define DD 64
#define BN  2048        // BB*NN
#define BND 131072      // BN*DD
#define BNDD 8388608    // BND*DD

// out layout: prediction[BND], target[BND], A_new[BN*NN], W1n[BNDD], W2n[BNDD], W3n[BNDD]
#define OFF_T  (BND)
#define OFF_A  (2*BND)
#define OFF_W1 (4*BND)            // 2*BND + BN*NN = 4*BND
#define OFF_W2 (OFF_W1 + BNDD)
#define OFF_W3 (OFF_W2 + BNDD)

// k2 tiled smem layout (floats): Ks[128][65], Os[128][65], anew[16][128], wq[16][64]
#define K2_LDK   65
#define K2_OFF_OS   (NN * K2_LDK)
#define K2_OFF_AN   (2 * NN * K2_LDK)
#define K2_OFF_WQ   (K2_OFF_AN + 16 * NN)
#define K2_SMEM_FLOATS (K2_OFF_WQ + 16 * DD)
#define K2_SMEM_BYTES  (K2_SMEM_FLOATS * 4)

// scratch (static device globals; no allocation)
__device__ float g_q[BND];
__device__ float g_k[BND];
__device__ float g_coef[BND];
__device__ float g_noisy[BND];
__device__ float g_pbn_m[BN];
__device__ float g_pbn_e[BN];
__device__ float g_pbn_e2[BN];
__device__ float g_mag[BB];
__device__ float g_gmask[DD];
__device__ float g_std;
__device__ unsigned g_cnt = 0;

__device__ __forceinline__ float wredMax(float v) {
    #pragma unroll
    for (int o = 16; o; o >>= 1) v = fmaxf(v, __shfl_xor_sync(0xffffffffu, v, o));
    return v;
}
__device__ __forceinline__ float wredSum(float v) {
    #pragma unroll
    for (int o = 16; o; o >>= 1) v += __shfl_xor_sync(0xffffffffu, v, o);
    return v;
}

// ---------------------------------------------------------------------------
// K1: per (b,n) three matvecs (pred/k/q). 1 bn per 96-thread block with
// j-loop split in half (2 j-halves x 48 output groups) -> grid 2048,
// 14 blocks/SM = single wave.
// ---------------------------------------------------------------------------
__global__ void __launch_bounds__(96, 14) k1_qkp(
    const float* __restrict__ state,
    const float* __restrict__ W1, const float* __restrict__ W2, const float* __restrict__ W3,
    float* __restrict__ out)
{
    int t   = threadIdx.x;
    int jh  = t / 48;         // 0..1 : j-half
    int r   = t % 48;
    int x   = r >> 4;         // 0: W1(pred), 1: W2(k), 2: W3(q)
    int kk  = r & 15;         // float4 column group
    int bn  = blockIdx.x;

    __shared__ float  s[DD];
    __shared__ float4 part[2][48];

    if (t < DD) s[t] = state[bn * DD + t];
    __syncthreads();

    const float* Wp = (x == 0) ? W1 : ((x == 1) ? W2 : W3);
    const float4* Wb = (const float4*)(Wp + (size_t)bn * DD * DD) + kk;

    float4 acc = {0.f, 0.f, 0.f, 0.f};
    int j0 = jh * 32;
    #pragma unroll 8
    for (int j = j0; j < j0 + 32; j++) {
        float  sv = s[j];
        float4 w  = Wb[j * 16];
        acc.x += sv * w.x; acc.y += sv * w.y;
        acc.z += sv * w.z; acc.w += sv * w.w;
    }
    part[jh][r] = acc;
    __syncthreads();

    if (t < 48) {
        float4 a = part[0][r];
        float4 bq = part[1][r];
        float4 acc2 = { a.x + bq.x, a.y + bq.y, a.z + bq.z, a.w + bq.w };

        if (x == 0) {
            const float C = 1.8477590650225735f;  // sqrt(2+sqrt(2))
            float4 p;
            p.x = tanhf(acc2.x - tanhf(acc2.x) * 0.6f) * C;
            p.y = tanhf(acc2.y - tanhf(acc2.y) * 0.6f) * C;
            p.z = tanhf(acc2.z - tanhf(acc2.z) * 0.6f) * C;
            p.w = tanhf(acc2.w - tanhf(acc2.w) * 0.6f) * C;
            ((float4*)out)[bn * 16 + kk] = p;
        } else if (x == 1) {
            ((float4*)g_k)[bn * 16 + kk] = acc2;
        } else {
            ((float4*)g_q)[bn * 16 + kk] = acc2;
        }
    }
}

// ---------------------------------------------------------------------------
// K2 TILED: 128 blocks x 512 threads. Block = (b, 16 attention rows).
// K and output slices staged ONCE per block into padded smem; warp per row,
// softmax fully warp-local. Fused global stats via last-block-done.
// ---------------------------------------------------------------------------
__global__ void __launch_bounds__(512) k2_attn(
    const float* __restrict__ A,
    const float* __restrict__ noiseA,
    const float* __restrict__ outputv,
    const float* __restrict__ eye,
    const float* __restrict__ stomach,
    const float* __restrict__ state,
    const int* __restrict__ stepc,
    float* __restrict__ out)
{
    extern __shared__ float dsm[];
    float* Ks  = dsm;                 // [128][65]
    float* Os  = dsm + K2_OFF_OS;     // [128][65]
    float* ans = dsm + K2_OFF_AN;     // [16][128]
    float* wq  = dsm + K2_OFF_WQ;     // [16][64]

    int t  = threadIdx.x;
    int w  = t >> 5;                  // warp 0..15 = row within tile
    int l  = t & 31;
    int b  = blockIdx.x >> 3;
    int n  = (blockIdx.x & 7) * 16 + w;
    int bn = b * NN + n;

    // stage K and output slices of batch b (scalar smem stores due to padding)
    {
        const float4* gk = (const float4*)(g_k + (size_t)b * NN * DD);
        const float4* go = (const float4*)(outputv + (size_t)b * NN * DD);
        for (int i = t; i < NN * DD / 4; i += 512) {
            int row = i >> 4;
            int c4  = (i & 15) * 4;
            float4 kv = gk[i];
            float4 ov = go[i];
            float* kd = Ks + row * K2_LDK + c4;
            kd[0] = kv.x; kd[1] = kv.y; kd[2] = kv.z; kd[3] = kv.w;
            float* od = Os + row * K2_LDK + c4;
            od[0] = ov.x; od[1] = ov.y; od[2] = ov.z; od[3] = ov.w;
        }
        if (l < 16) {
            float4 qv = ((const float4*)(g_q + (size_t)bn * DD))[l];
            float* qd = wq + w * DD + l * 4;
            qd[0] = qv.x; qd[1] = qv.y; qd[2] = qv.z; qd[3] = qv.w;
        }
    }
    __syncthreads();

    float ae = 0.f, ae2 = 0.f, am = 0.f;

    if (n < 2) {
        #pragma unroll
        for (int r = 0; r < 4; r++)
            out[OFF_A + (size_t)bn * NN + l + 32 * r] = 0.f;
        const float* env = (n == 0) ? (eye + b * DD) : (stomach + b * DD);
        #pragma unroll
        for (int r = 0; r < 2; r++) {
            int col = l + 32 * r;
            float tv = env[col];
            out[OFF_T + bn * DD + col] = tv;
            float err = out[bn * DD + col] - tv;
            ae += err; ae2 += err * err;
            am += fabsf(state[bn * DD + col]);
        }
    } else {
        // raw_A row: lane owns m = l + 32r (conflict-free smem banks)
        float raw[4];
        const float* qv = wq + w * DD;
        #pragma unroll
        for (int r = 0; r < 4; r++) {
            int m = l + 32 * r;
            const float* kr = Ks + m * K2_LDK;
            float dot = 0.f;
            #pragma unroll 8
            for (int j = 0; j < DD; j++) dot += qv[j] * kr[j];
            raw[r] = dot * 0.125f + noiseA[(size_t)bn * NN + m] * 1e-5f;
        }

        float mx = fmaxf(fmaxf(raw[0], raw[1]), fmaxf(raw[2], raw[3]));
        mx = wredMax(mx);

        float e[4], ls = 0.f;
        #pragma unroll
        for (int r = 0; r < 4; r++) { e[r] = expf(raw[r] - mx); ls += e[r]; }
        float sum = wredSum(ls);

        float maxpd = 1.0f / sum;      // max element has e == 1.0f exactly
        float lek = 0.f;
        float ek[4];
        #pragma unroll
        for (int r = 0; r < 4; r++) {
            float pd = e[r] / sum;
            bool keep = (pd > (1.0f / 129.0f)) || (pd == maxpd);
            ek[r] = keep ? e[r] : 0.f;
            lek += ek[r];
        }
        float sum2 = wredSum(lek);

        #pragma unroll
        for (int r = 0; r < 4; r++) {
            int m = l + 32 * r;
            float P  = ek[r] / sum2;
            float an = A[(size_t)bn * NN + m] * 0.99f + P * 0.01f;
            out[OFF_A + (size_t)bn * NN + m] = an;
            ans[w * NN + m] = an;
        }
        __syncwarp();

        // target: lane computes cols l and l+32 (conflict-free Os reads)
        const float* aw = ans + w * NN;
        #pragma unroll
        for (int r = 0; r < 2; r++) {
            int col = l + 32 * r;
            float acc = 0.f;
            #pragma unroll 8
            for (int m = 0; m < NN; m++)
                acc += aw[m] * Os[m * K2_LDK + col];
            out[OFF_T + bn * DD + col] = acc;
            float err = out[bn * DD + col] - acc;
            ae += err; ae2 += err * err;
            am += fabsf(state[bn * DD + col]);
        }
    }

    // per-bn stats: pure warp reduce, lane 0 writes
    ae  = wredSum(ae);
    ae2 = wredSum(ae2);
    am  = wredSum(am);
    if (l == 0) {
        g_pbn_e[bn]  = ae;
        g_pbn_e2[bn] = ae2;
        g_pbn_m[bn]  = am;
    }

    // last-block final reduction
    __shared__ int isLast;
    __syncthreads();
    if (t == 0) {
        __threadfence();
        unsigned old = atomicAdd(&g_cnt, 1u);
        isLast = (old == 127u) ? 1 : 0;
    }
    __syncthreads();
    if (isLast) {
        // per-b mag: 8 lanes per b, each sums 16 entries
        if (t < 128) {
            int bb = t >> 3, j = t & 7;
            float s = 0.f;
            int base = bb * NN + j * 16;
            #pragma unroll
            for (int i = 0; i < 16; i++) s += g_pbn_m[base + i];
            #pragma unroll
            for (int o = 4; o; o >>= 1) s += __shfl_xor_sync(0xffffffffu, s, o);
            if (j == 0) g_mag[bb] = s;
        }
        // global err sums over 2048 partials with all 512 threads
        {
            float e = 0.f, e2 = 0.f;
            for (int i = t; i < BN; i += 512) { e += g_pbn_e[i]; e2 += g_pbn_e2[i]; }
            e = wredSum(e); e2 = wredSum(e2);
            __shared__ float r0[16], r1[16];
            if (l == 0) { r0[w] = e; r1[w] = e2; }
            __syncthreads();
            if (t == 0) {
                float E = 0.f, E2 = 0.f;
                #pragma unroll
                for (int i = 0; i < 16; i++) { E += r0[i]; E2 += r1[i]; }
                const float M = (float)BND;
                float var = (E2 - E * E / M) / (M - 1.0f);
                g_std = sqrtf(fmaxf(var, 0.f));
                g_cnt = 0u;   // reset for next graph replay
            }
        }
        // travelling gaussian column mask
        if (t < DD) {
            float scf    = (float)(*stepc) + 1.0f;
            float center = fmodf(scf * 0.5f, 64.0f);
            float d = fabsf((float)t - center);
            d = fminf(d, 64.f - d);
            g_gmask[t] = expf(-d * d / 0.020001f);
        }
    }
}

// ---------------------------------------------------------------------------
// K4: warp per (b,n): E_curr softmax over D, Eb EMA, plasticity/mask,
// noisy_state, outer-product rms factorization -> coef, noisy.
// ---------------------------------------------------------------------------
__global__ void __launch_bounds__(256) k4_coef(
    const float* __restrict__ state,
    const float* __restrict__ Ebase,
    const float* __restrict__ n1raw,
    const float* __restrict__ n2raw,
    const float* __restrict__ out)
{
    int bn   = blockIdx.x * 8 + (threadIdx.x >> 5);
    int lane = threadIdx.x & 31;
    int b    = bn >> 7;
    int g0   = bn * DD + lane;
    int g1   = g0 + 32;

    float errA = out[g0] - out[OFF_T + g0];
    float errB = out[g1] - out[OFF_T + g1];

    float mx = wredMax(fmaxf(errA, errB));
    float exA = expf(errA - mx), exB = expf(errB - mx);
    float sm = wredSum(exA + exB);
    float EcA = exA / sm, EcB = exB / sm;

    float Eb0A = Ebase[g0], Eb0B = Ebase[g1];
    float EbA = (Eb0A == 0.f) ? EcA : Eb0A;
    float EbB = (Eb0B == 0.f) ? EcB : Eb0B;
    EbA = EbA * 0.95f + 0.05f * EcA;
    EbB = EbB * 0.95f + 0.05f * EcB;
    float advA = EcA - EbA, advB = EcB - EbB;
    float plA = 1.f + advA * rsqrtf(advA * advA + 1e-6f);
    float plB = 1.f + advB * rsqrtf(advB * advB + 1e-6f);
    float mkA = (EbA > 0.f) ? 1.f : 0.f;
    float mkB = (EbB > 0.f) ? 1.f : 0.f;

    float inv_mag = 1.f / (1.f + g_mag[b]);
    float sd = g_std * 0.8f;
    float nsA = state[g0] + n1raw[g0] * inv_mag + n2raw[g0] * sd;
    float nsB = state[g1] + n1raw[g1] * inv_mag + n2raw[g1] * sd;

    float se2 = wredSum(errA * errA + errB * errB);
    float sn2 = wredSum(nsA * nsA + nsB * nsB);
    float rn = rsqrtf((se2 * (1.f / DD)) * (sn2 * (1.f / DD)) + 1e-6f);

    g_coef[g0]  = -errA * rn * plA * mkA;
    g_coef[g1]  = -errB * rn * plB * mkB;
    g_noisy[g0] = nsA;
    g_noisy[g1] = nsB;
}

// ---------------------------------------------------------------------------
// K5: fused grads + momentum + gaussian mask + W update + row rms.
// Reversed walk; __ldcs on M, __stcs on stores. (proven (256,7) version)
// ---------------------------------------------------------------------------
__device__ __forceinline__ float newW(float w, float wlat, float m, float h, float g) {
    float grad = h + 0.01f * wlat - 0.01f * w;     // LAT_DECAY*W_lat - WD*W_self
    return w + 0.0033f * (m * 0.4f + 0.6f * grad * g);
}

__global__ void __launch_bounds__(256, 7) k5_update(
    const float* __restrict__ W1, const float* __restrict__ W2, const float* __restrict__ W3,
    const float* __restrict__ M1, const float* __restrict__ M2, const float* __restrict__ M3,
    float* __restrict__ out)
{
    int t   = threadIdx.x;
    int tx  = t & 15;
    int blk = (int)gridDim.x - 1 - (int)blockIdx.x;   // reversed walk
    int row = blk * 16 + (t >> 4);         // 0..BND-1  (b,n,i)
    int bn  = row >> 6;
    size_t b4 = (size_t)row * 16 + tx;     // float4 index into (BND x D) matrices

    float4 w1 = ((const float4*)W1)[b4];
    float4 w2 = ((const float4*)W2)[b4];
    float4 w3 = ((const float4*)W3)[b4];

    float  c  = g_coef[row];
    float4 ns = ((const float4*)g_noisy)[bn * 16 + tx];
    float4 gm = ((const float4*)g_gmask)[tx];
    float4 h  = { c * ns.x, c * ns.y, c * ns.z, c * ns.w };

    // --- W1 update ---
    {
        float4 m1 = __ldcs(((const float4*)M1) + b4);
        float4 t1;
        t1.x = newW(w1.x, w3.x, m1.x, h.x, gm.x);
        t1.y = newW(w1.y, w3.y, m1.y, h.y, gm.y);
        t1.z = newW(w1.z, w3.z, m1.z, h.z, gm.z);
        t1.w = newW(w1.w, w3.w, m1.w, h.w, gm.w);
        float s1 = t1.x*t1.x + t1.y*t1.y + t1.z*t1.z + t1.w*t1.w;
        #pragma unroll
        for (int o = 8; o; o >>= 1) s1 += __shfl_xor_sync(0xffffffffu, s1, o);
        float r1 = rsqrtf(s1 * (1.f / 64.f) + 1e-6f);
        float4 o1 = { t1.x*r1, t1.y*r1, t1.z*r1, t1.w*r1 };
        __stcs(((float4*)(out + OFF_W1)) + b4, o1);
    }
    // --- W2 update ---
    {
        float4 m2 = __ldcs(((const float4*)M2) + b4);
        float4 t2;
        t2.x = newW(w2.x, w1.x, m2.x, h.x, gm.x);
        t2.y = newW(w2.y, w1.y, m2.y, h.y, gm.y);
        t2.z = newW(w2.z, w1.z, m2.z, h.z, gm.z);
        t2.w = newW(w2.w, w1.w, m2.w, h.w, gm.w);
        float s2 = t2.x*t2.x + t2.y*t2.y + t2.z*t2.z + t2.w*t2.w;
        #pragma unroll
        for (int o = 8; o; o >>= 1) s2 += __shfl_xor_sync(0xffffffffu, s2, o);
        float r2 = rsqrtf(s2 * (1.f / 64.f) + 1e-6f);
        float4 o2 = { t2.x*r2, t2.y*r2, t2.z*r2, t2.w*r2 };
        __stcs(((float4*)(out + OFF_W2)) + b4, o2);
    }
    // --- W3 update ---
    {
        float4 m3 = __ldcs(((const float4*)M3) + b4);
        float4 t3;
        t3.x = newW(w3.x, w2.x, m3.x, h.x, gm.x);
        t3.y = newW(w3.y, w2.y, m3.y, h.y, gm.y);
        t3.z = newW(w3.z, w2.z, m3.z, h.z, gm.z);
        t3.w = newW(w3.w, w2.w, m3.w, h.w, gm.w);
        float s3 = t3.x*t3.x + t3.y*t3.y + t3.z*t3.z + t3.w*t3.w;
        #pragma unroll
        for (int o = 8; o; o >>= 1) s3 += __shfl_xor_sync(0xffffffffu, s3, o);
        float r3 = rsqrtf(s3 * (1.f / 64.f) + 1e-6f);
        float4 o3 = { t3.x*r3, t3.y*r3, t3.z*r3, t3.w*r3 };
        __stcs(((float4*)(out + OFF_W3)) + b4, o3);
    }
}

// ---------------------------------------------------------------------------
extern "C" void kernel_launch(void* const* d_in, const int* in_sizes, int n_in,
                              void* d_out, int out_size)
{
    const float* eye     = (const float*)d_in[0];
    const float* stomach = (const float*)d_in[1];
    const float* state   = (const float*)d_in[2];
    const float* outputv = (const float*)d_in[3];
    const float* W1      = (const float*)d_in[4];
    const float* W2      = (const float*)d_in[5];
    const float* W3      = (const float*)d_in[6];
    const float* M1      = (const float*)d_in[7];
    const float* M2      = (const float*)d_in[8];
    const float* M3      = (const float*)d_in[9];
    const float* Ebase   = (const float*)d_in[10];
    const float* A       = (const float*)d_in[11];
    const float* noiseA  = (const float*)d_in[12];
    const float* n1raw   = (const float*)d_in[13];
    const float* n2raw   = (const float*)d_in[14];
    const int*   stepc   = (const int*)d_in[15];
    float* out = (float*)d_out;

    cudaFuncSetAttribute(k2_attn, cudaFuncAttributeMaxDynamicSharedMemorySize,
                         K2_SMEM_BYTES);

    k1_qkp<<<BN, 96>>>(state, W1, W2, W3, out);
    k2_attn<<<128, 512, K2_SMEM_BYTES>>>(A, noiseA, outputv, eye, stomach, state, stepc, out);
    k4_coef<<<BN / 8, 256>>>(state, Ebase, n1raw, n2raw, out);
    k5_update<<<BND / 16, 256>>>(W1, W2, W3, M1, M2, M3, out);
}

// round 16
// speedup vs baseline: 1.2107x; 1.0203x over previous
#include <cuda_runtime.h>
#include <math.h>

#define BB 16
#define NN 128
#define DD 64
#define BN  2048        // BB*NN
#define BND 131072      // BN*DD
#define BNDD 8388608    // BND*DD

// out layout: prediction[BND], target[BND], A_new[BN*NN], W1n[BNDD], W2n[BNDD], W3n[BNDD]
#define OFF_T  (BND)
#define OFF_A  (2*BND)
#define OFF_W1 (4*BND)            // 2*BND + BN*NN = 4*BND
#define OFF_W2 (OFF_W1 + BNDD)
#define OFF_W3 (OFF_W2 + BNDD)

// k2 tiled smem layout (floats): Ks[128][65], Os[128][65], anew[16][128], wq[16][64]
#define K2_LDK   65
#define K2_OFF_OS   (NN * K2_LDK)
#define K2_OFF_AN   (2 * NN * K2_LDK)
#define K2_OFF_WQ   (K2_OFF_AN + 16 * NN)
#define K2_SMEM_FLOATS (K2_OFF_WQ + 16 * DD)
#define K2_SMEM_BYTES  (K2_SMEM_FLOATS * 4)

// scratch (static device globals; no allocation)
__device__ float g_q[BND];
__device__ float g_k[BND];
__device__ float g_coef[BND];
__device__ float g_noisy[BND];
__device__ float g_pbn_m[BN];
__device__ float g_pbn_e[BN];
__device__ float g_pbn_e2[BN];
__device__ float g_mag[BB];
__device__ float g_gmask[DD];
__device__ float g_std;
__device__ unsigned g_cnt = 0;

__device__ __forceinline__ float wredMax(float v) {
    #pragma unroll
    for (int o = 16; o; o >>= 1) v = fmaxf(v, __shfl_xor_sync(0xffffffffu, v, o));
    return v;
}
__device__ __forceinline__ float wredSum(float v) {
    #pragma unroll
    for (int o = 16; o; o >>= 1) v += __shfl_xor_sync(0xffffffffu, v, o);
    return v;
}

// ---------------------------------------------------------------------------
// K1: per (b,n) three matvecs (pred/k/q). 4-way j-split: 192 threads per bn
// (4 j-quarters x 48 output groups), grid 2048, min-blocks 9 -> 1728 thr/SM
// (+30% concurrency vs the 96-thread version). smem partial combine.
// ---------------------------------------------------------------------------
__global__ void __launch_bounds__(192, 9) k1_qkp(
    const float* __restrict__ state,
    const float* __restrict__ W1, const float* __restrict__ W2, const float* __restrict__ W3,
    float* __restrict__ out)
{
    int t   = threadIdx.x;
    int jh  = t / 48;         // 0..3 : j-quarter
    int r   = t % 48;
    int x   = r >> 4;         // 0: W1(pred), 1: W2(k), 2: W3(q)
    int kk  = r & 15;         // float4 column group
    int bn  = blockIdx.x;

    __shared__ float  s[DD];
    __shared__ float4 part[4][48];

    if (t < DD) s[t] = state[bn * DD + t];
    __syncthreads();

    const float* Wp = (x == 0) ? W1 : ((x == 1) ? W2 : W3);
    const float4* Wb = (const float4*)(Wp + (size_t)bn * DD * DD) + kk;

    float4 acc = {0.f, 0.f, 0.f, 0.f};
    int j0 = jh * 16;
    #pragma unroll 8
    for (int j = j0; j < j0 + 16; j++) {
        float  sv = s[j];
        float4 w  = Wb[j * 16];
        acc.x += sv * w.x; acc.y += sv * w.y;
        acc.z += sv * w.z; acc.w += sv * w.w;
    }
    part[jh][r] = acc;
    __syncthreads();

    if (t < 48) {
        float4 p0 = part[0][r];
        float4 p1 = part[1][r];
        float4 p2 = part[2][r];
        float4 p3 = part[3][r];
        float4 acc2 = { ((p0.x + p1.x) + p2.x) + p3.x,
                        ((p0.y + p1.y) + p2.y) + p3.y,
                        ((p0.z + p1.z) + p2.z) + p3.z,
                        ((p0.w + p1.w) + p2.w) + p3.w };

        if (x == 0) {
            const float C = 1.8477590650225735f;  // sqrt(2+sqrt(2))
            float4 p;
            p.x = tanhf(acc2.x - tanhf(acc2.x) * 0.6f) * C;
            p.y = tanhf(acc2.y - tanhf(acc2.y) * 0.6f) * C;
            p.z = tanhf(acc2.z - tanhf(acc2.z) * 0.6f) * C;
            p.w = tanhf(acc2.w - tanhf(acc2.w) * 0.6f) * C;
            ((float4*)out)[bn * 16 + kk] = p;
        } else if (x == 1) {
            ((float4*)g_k)[bn * 16 + kk] = acc2;
        } else {
            ((float4*)g_q)[bn * 16 + kk] = acc2;
        }
    }
}

// ---------------------------------------------------------------------------
// K2 TILED: 128 blocks x 512 threads. Block = (b, 16 attention rows).
// K and output slices staged ONCE per block into padded smem; warp per row,
// softmax fully warp-local. Fused global stats via last-block-done.
// ---------------------------------------------------------------------------
__global__ void __launch_bounds__(512) k2_attn(
    const float* __restrict__ A,
    const float* __restrict__ noiseA,
    const float* __restrict__ outputv,
    const float* __restrict__ eye,
    const float* __restrict__ stomach,
    const float* __restrict__ state,
    const int* __restrict__ stepc,
    float* __restrict__ out)
{
    extern __shared__ float dsm[];
    float* Ks  = dsm;                 // [128][65]
    float* Os  = dsm + K2_OFF_OS;     // [128][65]
    float* ans = dsm + K2_OFF_AN;     // [16][128]
    float* wq  = dsm + K2_OFF_WQ;     // [16][64]

    int t  = threadIdx.x;
    int w  = t >> 5;                  // warp 0..15 = row within tile
    int l  = t & 31;
    int b  = blockIdx.x >> 3;
    int n  = (blockIdx.x & 7) * 16 + w;
    int bn = b * NN + n;

    // stage K and output slices of batch b (scalar smem stores due to padding)
    {
        const float4* gk = (const float4*)(g_k + (size_t)b * NN * DD);
        const float4* go = (const float4*)(outputv + (size_t)b * NN * DD);
        for (int i = t; i < NN * DD / 4; i += 512) {
            int row = i >> 4;
            int c4  = (i & 15) * 4;
            float4 kv = gk[i];
            float4 ov = go[i];
            float* kd = Ks + row * K2_LDK + c4;
            kd[0] = kv.x; kd[1] = kv.y; kd[2] = kv.z; kd[3] = kv.w;
            float* od = Os + row * K2_LDK + c4;
            od[0] = ov.x; od[1] = ov.y; od[2] = ov.z; od[3] = ov.w;
        }
        if (l < 16) {
            float4 qv = ((const float4*)(g_q + (size_t)bn * DD))[l];
            float* qd = wq + w * DD + l * 4;
            qd[0] = qv.x; qd[1] = qv.y; qd[2] = qv.z; qd[3] = qv.w;
        }
    }
    __syncthreads();

    float ae = 0.f, ae2 = 0.f, am = 0.f;

    if (n < 2) {
        #pragma unroll
        for (int r = 0; r < 4; r++)
            out[OFF_A + (size_t)bn * NN + l + 32 * r] = 0.f;
        const float* env = (n == 0) ? (eye + b * DD) : (stomach + b * DD);
        #pragma unroll
        for (int r = 0; r < 2; r++) {
            int col = l + 32 * r;
            float tv = env[col];
            out[OFF_T + bn * DD + col] = tv;
            float err = out[bn * DD + col] - tv;
            ae += err; ae2 += err * err;
            am += fabsf(state[bn * DD + col]);
        }
    } else {
        // raw_A row: lane owns m = l + 32r (conflict-free smem banks)
        float raw[4];
        const float* qv = wq + w * DD;
        #pragma unroll
        for (int r = 0; r < 4; r++) {
            int m = l + 32 * r;
            const float* kr = Ks + m * K2_LDK;
            float dot = 0.f;
            #pragma unroll 8
            for (int j = 0; j < DD; j++) dot += qv[j] * kr[j];
            raw[r] = dot * 0.125f + noiseA[(size_t)bn * NN + m] * 1e-5f;
        }

        float mx = fmaxf(fmaxf(raw[0], raw[1]), fmaxf(raw[2], raw[3]));
        mx = wredMax(mx);

        float e[4], ls = 0.f;
        #pragma unroll
        for (int r = 0; r < 4; r++) { e[r] = expf(raw[r] - mx); ls += e[r]; }
        float sum = wredSum(ls);

        float maxpd = 1.0f / sum;      // max element has e == 1.0f exactly
        float lek = 0.f;
        float ek[4];
        #pragma unroll
        for (int r = 0; r < 4; r++) {
            float pd = e[r] / sum;
            bool keep = (pd > (1.0f / 129.0f)) || (pd == maxpd);
            ek[r] = keep ? e[r] : 0.f;
            lek += ek[r];
        }
        float sum2 = wredSum(lek);

        #pragma unroll
        for (int r = 0; r < 4; r++) {
            int m = l + 32 * r;
            float P  = ek[r] / sum2;
            float an = A[(size_t)bn * NN + m] * 0.99f + P * 0.01f;
            out[OFF_A + (size_t)bn * NN + m] = an;
            ans[w * NN + m] = an;
        }
        __syncwarp();

        // target: lane computes cols l and l+32 (conflict-free Os reads)
        const float* aw = ans + w * NN;
        #pragma unroll
        for (int r = 0; r < 2; r++) {
            int col = l + 32 * r;
            float acc = 0.f;
            #pragma unroll 8
            for (int m = 0; m < NN; m++)
                acc += aw[m] * Os[m * K2_LDK + col];
            out[OFF_T + bn * DD + col] = acc;
            float err = out[bn * DD + col] - acc;
            ae += err; ae2 += err * err;
            am += fabsf(state[bn * DD + col]);
        }
    }

    // per-bn stats: pure warp reduce, lane 0 writes
    ae  = wredSum(ae);
    ae2 = wredSum(ae2);
    am  = wredSum(am);
    if (l == 0) {
        g_pbn_e[bn]  = ae;
        g_pbn_e2[bn] = ae2;
        g_pbn_m[bn]  = am;
    }

    // last-block final reduction
    __shared__ int isLast;
    __syncthreads();
    if (t == 0) {
        __threadfence();
        unsigned old = atomicAdd(&g_cnt, 1u);
        isLast = (old == 127u) ? 1 : 0;
    }
    __syncthreads();
    if (isLast) {
        // per-b mag: 8 lanes per b, each sums 16 entries
        if (t < 128) {
            int bb = t >> 3, j = t & 7;
            float s = 0.f;
            int base = bb * NN + j * 16;
            #pragma unroll
            for (int i = 0; i < 16; i++) s += g_pbn_m[base + i];
            #pragma unroll
            for (int o = 4; o; o >>= 1) s += __shfl_xor_sync(0xffffffffu, s, o);
            if (j == 0) g_mag[bb] = s;
        }
        // global err sums over 2048 partials with all 512 threads
        {
            float e = 0.f, e2 = 0.f;
            for (int i = t; i < BN; i += 512) { e += g_pbn_e[i]; e2 += g_pbn_e2[i]; }
            e = wredSum(e); e2 = wredSum(e2);
            __shared__ float r0[16], r1[16];
            if (l == 0) { r0[w] = e; r1[w] = e2; }
            __syncthreads();
            if (t == 0) {
                float E = 0.f, E2 = 0.f;
                #pragma unroll
                for (int i = 0; i < 16; i++) { E += r0[i]; E2 += r1[i]; }
                const float M = (float)BND;
                float var = (E2 - E * E / M) / (M - 1.0f);
                g_std = sqrtf(fmaxf(var, 0.f));
                g_cnt = 0u;   // reset for next graph replay
            }
        }
        // travelling gaussian column mask
        if (t < DD) {
            float scf    = (float)(*stepc) + 1.0f;
            float center = fmodf(scf * 0.5f, 64.0f);
            float d = fabsf((float)t - center);
            d = fminf(d, 64.f - d);
            g_gmask[t] = expf(-d * d / 0.020001f);
        }
    }
}

// ---------------------------------------------------------------------------
// K4: warp per (b,n): E_curr softmax over D, Eb EMA, plasticity/mask,
// noisy_state, outer-product rms factorization -> coef, noisy.
// ---------------------------------------------------------------------------
__global__ void __launch_bounds__(256) k4_coef(
    const float* __restrict__ state,
    const float* __restrict__ Ebase,
    const float* __restrict__ n1raw,
    const float* __restrict__ n2raw,
    const float* __restrict__ out)
{
    int bn   = blockIdx.x * 8 + (threadIdx.x >> 5);
    int lane = threadIdx.x & 31;
    int b    = bn >> 7;
    int g0   = bn * DD + lane;
    int g1   = g0 + 32;

    float errA = out[g0] - out[OFF_T + g0];
    float errB = out[g1] - out[OFF_T + g1];

    float mx = wredMax(fmaxf(errA, errB));
    float exA = expf(errA - mx), exB = expf(errB - mx);
    float sm = wredSum(exA + exB);
    float EcA = exA / sm, EcB = exB / sm;

    float Eb0A = Ebase[g0], Eb0B = Ebase[g1];
    float EbA = (Eb0A == 0.f) ? EcA : Eb0A;
    float EbB = (Eb0B == 0.f) ? EcB : Eb0B;
    EbA = EbA * 0.95f + 0.05f * EcA;
    EbB = EbB * 0.95f + 0.05f * EcB;
    float advA = EcA - EbA, advB = EcB - EbB;
    float plA = 1.f + advA * rsqrtf(advA * advA + 1e-6f);
    float plB = 1.f + advB * rsqrtf(advB * advB + 1e-6f);
    float mkA = (EbA > 0.f) ? 1.f : 0.f;
    float mkB = (EbB > 0.f) ? 1.f : 0.f;

    float inv_mag = 1.f / (1.f + g_mag[b]);
    float sd = g_std * 0.8f;
    float nsA = state[g0] + n1raw[g0] * inv_mag + n2raw[g0] * sd;
    float nsB = state[g1] + n1raw[g1] * inv_mag + n2raw[g1] * sd;

    float se2 = wredSum(errA * errA + errB * errB);
    float sn2 = wredSum(nsA * nsA + nsB * nsB);
    float rn = rsqrtf((se2 * (1.f / DD)) * (sn2 * (1.f / DD)) + 1e-6f);

    g_coef[g0]  = -errA * rn * plA * mkA;
    g_coef[g1]  = -errB * rn * plB * mkB;
    g_noisy[g0] = nsA;
    g_noisy[g1] = nsB;
}

// ---------------------------------------------------------------------------
// K5: fused grads + momentum + gaussian mask + W update + row rms.
// Reversed walk; __ldcs on M, __stcs on stores. (proven (256,7) version)
// ---------------------------------------------------------------------------
__device__ __forceinline__ float newW(float w, float wlat, float m, float h, float g) {
    float grad = h + 0.01f * wlat - 0.01f * w;     // LAT_DECAY*W_lat - WD*W_self
    return w + 0.0033f * (m * 0.4f + 0.6f * grad * g);
}

__global__ void __launch_bounds__(256, 7) k5_update(
    const float* __restrict__ W1, const float* __restrict__ W2, const float* __restrict__ W3,
    const float* __restrict__ M1, const float* __restrict__ M2, const float* __restrict__ M3,
    float* __restrict__ out)
{
    int t   = threadIdx.x;
    int tx  = t & 15;
    int blk = (int)gridDim.x - 1 - (int)blockIdx.x;   // reversed walk
    int row = blk * 16 + (t >> 4);         // 0..BND-1  (b,n,i)
    int bn  = row >> 6;
    size_t b4 = (size_t)row * 16 + tx;     // float4 index into (BND x D) matrices

    float4 w1 = ((const float4*)W1)[b4];
    float4 w2 = ((const float4*)W2)[b4];
    float4 w3 = ((const float4*)W3)[b4];

    float  c  = g_coef[row];
    float4 ns = ((const float4*)g_noisy)[bn * 16 + tx];
    float4 gm = ((const float4*)g_gmask)[tx];
    float4 h  = { c * ns.x, c * ns.y, c * ns.z, c * ns.w };

    // --- W1 update ---
    {
        float4 m1 = __ldcs(((const float4*)M1) + b4);
        float4 t1;
        t1.x = newW(w1.x, w3.x, m1.x, h.x, gm.x);
        t1.y = newW(w1.y, w3.y, m1.y, h.y, gm.y);
        t1.z = newW(w1.z, w3.z, m1.z, h.z, gm.z);
        t1.w = newW(w1.w, w3.w, m1.w, h.w, gm.w);
        float s1 = t1.x*t1.x + t1.y*t1.y + t1.z*t1.z + t1.w*t1.w;
        #pragma unroll
        for (int o = 8; o; o >>= 1) s1 += __shfl_xor_sync(0xffffffffu, s1, o);
        float r1 = rsqrtf(s1 * (1.f / 64.f) + 1e-6f);
        float4 o1 = { t1.x*r1, t1.y*r1, t1.z*r1, t1.w*r1 };
        __stcs(((float4*)(out + OFF_W1)) + b4, o1);
    }
    // --- W2 update ---
    {
        float4 m2 = __ldcs(((const float4*)M2) + b4);
        float4 t2;
        t2.x = newW(w2.x, w1.x, m2.x, h.x, gm.x);
        t2.y = newW(w2.y, w1.y, m2.y, h.y, gm.y);
        t2.z = newW(w2.z, w1.z, m2.z, h.z, gm.z);
        t2.w = newW(w2.w, w1.w, m2.w, h.w, gm.w);
        float s2 = t2.x*t2.x + t2.y*t2.y + t2.z*t2.z + t2.w*t2.w;
        #pragma unroll
        for (int o = 8; o; o >>= 1) s2 += __shfl_xor_sync(0xffffffffu, s2, o);
        float r2 = rsqrtf(s2 * (1.f / 64.f) + 1e-6f);
        float4 o2 = { t2.x*r2, t2.y*r2, t2.z*r2, t2.w*r2 };
        __stcs(((float4*)(out + OFF_W2)) + b4, o2);
    }
    // --- W3 update ---
    {
        float4 m3 = __ldcs(((const float4*)M3) + b4);
        float4 t3;
        t3.x = newW(w3.x, w2.x, m3.x, h.x, gm.x);
        t3.y = newW(w3.y, w2.y, m3.y, h.y, gm.y);
        t3.z = newW(w3.z, w2.z, m3.z, h.z, gm.z);
        t3.w = newW(w3.w, w2.w, m3.w, h.w, gm.w);
        float s3 = t3.x*t3.x + t3.y*t3.y + t3.z*t3.z + t3.w*t3.w;
        #pragma unroll
        for (int o = 8; o; o >>= 1) s3 += __shfl_xor_sync(0xffffffffu, s3, o);
        float r3 = rsqrtf(s3 * (1.f / 64.f) + 1e-6f);
        float4 o3 = { t3.x*r3, t3.y*r3, t3.z*r3, t3.w*r3 };
        __stcs(((float4*)(out + OFF_W3)) + b4, o3);
    }
}

// ---------------------------------------------------------------------------
extern "C" void kernel_launch(void* const* d_in, const int* in_sizes, int n_in,
                              void* d_out, int out_size)
{
    const float* eye     = (const float*)d_in[0];
    const float* stomach = (const float*)d_in[1];
    const float* state   = (const float*)d_in[2];
    const float* outputv = (const float*)d_in[3];
    const float* W1      = (const float*)d_in[4];
    const float* W2      = (const float*)d_in[5];
    const float* W3      = (const float*)d_in[6];
    const float* M1      = (const float*)d_in[7];
    const float* M2      = (const float*)d_in[8];
    const float* M3      = (const float*)d_in[9];
    const float* Ebase   = (const float*)d_in[10];
    const float* A       = (const float*)d_in[11];
    const float* noiseA  = (const float*)d_in[12];
    const float* n1raw   = (const float*)d_in[13];
    const float* n2raw   = (const float*)d_in[14];
    const int*   stepc   = (const int*)d_in[15];
    float* out = (float*)d_out;

    cudaFuncSetAttribute(k2_attn, cudaFuncAttributeMaxDynamicSharedMemorySize,
                         K2_SMEM_BYTES);

    k1_qkp<<<BN, 192>>>(state, W1, W2, W3, out);
    k2_attn<<<128, 512, K2_SMEM_BYTES>>>(A, noiseA, outputv, eye, stomach, state, stepc, out);
    k4_coef<<<BN / 8, 256>>>(state, Ebase, n1raw, n2raw, out);
    k5_update<<<BND / 16, 256>>>(W1, W2, W3, M1, M2, M3, out);
}

// round 17
// speedup vs baseline: 1.2253x; 1.0121x over previous
#include <cuda_runtime.h>
#include <math.h>

#define BB 16
#define NN 128
#define DD 64
#define BN  2048        // BB*NN
#define BND 131072      // BN*DD
#define BNDD 8388608    // BND*DD

// out layout: prediction[BND], target[BND], A_new[BN*NN], W1n[BNDD], W2n[BNDD], W3n[BNDD]
#define OFF_T  (BND)
#define OFF_A  (2*BND)
#define OFF_W1 (4*BND)            // 2*BND + BN*NN = 4*BND
#define OFF_W2 (OFF_W1 + BNDD)
#define OFF_W3 (OFF_W2 + BNDD)

// k2 tiled smem layout (floats): Ks[128][65], Os[128][65], anew[16][128], wq[16][64]
#define K2_LDK   65
#define K2_OFF_OS   (NN * K2_LDK)
#define K2_OFF_AN   (2 * NN * K2_LDK)
#define K2_OFF_WQ   (K2_OFF_AN + 16 * NN)
#define K2_SMEM_FLOATS (K2_OFF_WQ + 16 * DD)
#define K2_SMEM_BYTES  (K2_SMEM_FLOATS * 4)

// scratch (static device globals; no allocation)
__device__ float g_q[BND];
__device__ float g_k[BND];
__device__ float g_coef[BND];
__device__ float g_noisy[BND];
__device__ float g_pbn_m[BN];
__device__ float g_pbn_e[BN];
__device__ float g_pbn_e2[BN];
__device__ float g_mag[BB];
__device__ float g_gmask[DD];
__device__ float g_std;
__device__ unsigned g_cnt = 0;

__device__ __forceinline__ float wredMax(float v) {
    #pragma unroll
    for (int o = 16; o; o >>= 1) v = fmaxf(v, __shfl_xor_sync(0xffffffffu, v, o));
    return v;
}
__device__ __forceinline__ float wredSum(float v) {
    #pragma unroll
    for (int o = 16; o; o >>= 1) v += __shfl_xor_sync(0xffffffffu, v, o);
    return v;
}

// ---------------------------------------------------------------------------
// K1: per (b,n) three matvecs (pred/k/q). 4-way j-split: 192 threads per bn,
// grid 2048. (R16 version)
// ---------------------------------------------------------------------------
__global__ void __launch_bounds__(192, 9) k1_qkp(
    const float* __restrict__ state,
    const float* __restrict__ W1, const float* __restrict__ W2, const float* __restrict__ W3,
    float* __restrict__ out)
{
    int t   = threadIdx.x;
    int jh  = t / 48;         // 0..3 : j-quarter
    int r   = t % 48;
    int x   = r >> 4;         // 0: W1(pred), 1: W2(k), 2: W3(q)
    int kk  = r & 15;         // float4 column group
    int bn  = blockIdx.x;

    __shared__ float  s[DD];
    __shared__ float4 part[4][48];

    if (t < DD) s[t] = state[bn * DD + t];
    __syncthreads();

    const float* Wp = (x == 0) ? W1 : ((x == 1) ? W2 : W3);
    const float4* Wb = (const float4*)(Wp + (size_t)bn * DD * DD) + kk;

    float4 acc = {0.f, 0.f, 0.f, 0.f};
    int j0 = jh * 16;
    #pragma unroll 8
    for (int j = j0; j < j0 + 16; j++) {
        float  sv = s[j];
        float4 w  = Wb[j * 16];
        acc.x += sv * w.x; acc.y += sv * w.y;
        acc.z += sv * w.z; acc.w += sv * w.w;
    }
    part[jh][r] = acc;
    __syncthreads();

    if (t < 48) {
        float4 p0 = part[0][r];
        float4 p1 = part[1][r];
        float4 p2 = part[2][r];
        float4 p3 = part[3][r];
        float4 acc2 = { ((p0.x + p1.x) + p2.x) + p3.x,
                        ((p0.y + p1.y) + p2.y) + p3.y,
                        ((p0.z + p1.z) + p2.z) + p3.z,
                        ((p0.w + p1.w) + p2.w) + p3.w };

        if (x == 0) {
            const float C = 1.8477590650225735f;  // sqrt(2+sqrt(2))
            float4 p;
            p.x = tanhf(acc2.x - tanhf(acc2.x) * 0.6f) * C;
            p.y = tanhf(acc2.y - tanhf(acc2.y) * 0.6f) * C;
            p.z = tanhf(acc2.z - tanhf(acc2.z) * 0.6f) * C;
            p.w = tanhf(acc2.w - tanhf(acc2.w) * 0.6f) * C;
            ((float4*)out)[bn * 16 + kk] = p;
        } else if (x == 1) {
            ((float4*)g_k)[bn * 16 + kk] = acc2;
        } else {
            ((float4*)g_q)[bn * 16 + kk] = acc2;
        }
    }
}

// ---------------------------------------------------------------------------
// K2 TILED (PDL secondary of k1): stages outputv tile BEFORE the grid
// dependency sync (independent of k1), then Ks/wq after. 128 x 512.
// ---------------------------------------------------------------------------
__global__ void __launch_bounds__(512) k2_attn(
    const float* __restrict__ A,
    const float* __restrict__ noiseA,
    const float* __restrict__ outputv,
    const float* __restrict__ eye,
    const float* __restrict__ stomach,
    const float* __restrict__ state,
    const int* __restrict__ stepc,
    float* __restrict__ out)
{
    extern __shared__ float dsm[];
    float* Ks  = dsm;                 // [128][65]
    float* Os  = dsm + K2_OFF_OS;     // [128][65]
    float* ans = dsm + K2_OFF_AN;     // [16][128]
    float* wq  = dsm + K2_OFF_WQ;     // [16][64]

    int t  = threadIdx.x;
    int w  = t >> 5;                  // warp 0..15 = row within tile
    int l  = t & 31;
    int b  = blockIdx.x >> 3;
    int n  = (blockIdx.x & 7) * 16 + w;
    int bn = b * NN + n;

    // ---- pre-sync: stage output slice (independent of k1) ----
    {
        const float4* go = (const float4*)(outputv + (size_t)b * NN * DD);
        for (int i = t; i < NN * DD / 4; i += 512) {
            int row = i >> 4;
            int c4  = (i & 15) * 4;
            float4 ov = go[i];
            float* od = Os + row * K2_LDK + c4;
            od[0] = ov.x; od[1] = ov.y; od[2] = ov.z; od[3] = ov.w;
        }
    }

    cudaGridDependencySynchronize();   // wait for k1 (g_k, g_q, prediction)

    // ---- post-sync: stage K slice and q rows ----
    {
        const float4* gk = (const float4*)(g_k + (size_t)b * NN * DD);
        for (int i = t; i < NN * DD / 4; i += 512) {
            int row = i >> 4;
            int c4  = (i & 15) * 4;
            float4 kv = gk[i];
            float* kd = Ks + row * K2_LDK + c4;
            kd[0] = kv.x; kd[1] = kv.y; kd[2] = kv.z; kd[3] = kv.w;
        }
        if (l < 16) {
            float4 qv = ((const float4*)(g_q + (size_t)bn * DD))[l];
            float* qd = wq + w * DD + l * 4;
            qd[0] = qv.x; qd[1] = qv.y; qd[2] = qv.z; qd[3] = qv.w;
        }
    }
    __syncthreads();

    float ae = 0.f, ae2 = 0.f, am = 0.f;

    if (n < 2) {
        #pragma unroll
        for (int r = 0; r < 4; r++)
            out[OFF_A + (size_t)bn * NN + l + 32 * r] = 0.f;
        const float* env = (n == 0) ? (eye + b * DD) : (stomach + b * DD);
        #pragma unroll
        for (int r = 0; r < 2; r++) {
            int col = l + 32 * r;
            float tv = env[col];
            out[OFF_T + bn * DD + col] = tv;
            float err = out[bn * DD + col] - tv;
            ae += err; ae2 += err * err;
            am += fabsf(state[bn * DD + col]);
        }
    } else {
        float raw[4];
        const float* qv = wq + w * DD;
        #pragma unroll
        for (int r = 0; r < 4; r++) {
            int m = l + 32 * r;
            const float* kr = Ks + m * K2_LDK;
            float dot = 0.f;
            #pragma unroll 8
            for (int j = 0; j < DD; j++) dot += qv[j] * kr[j];
            raw[r] = dot * 0.125f + noiseA[(size_t)bn * NN + m] * 1e-5f;
        }

        float mx = fmaxf(fmaxf(raw[0], raw[1]), fmaxf(raw[2], raw[3]));
        mx = wredMax(mx);

        float e[4], ls = 0.f;
        #pragma unroll
        for (int r = 0; r < 4; r++) { e[r] = expf(raw[r] - mx); ls += e[r]; }
        float sum = wredSum(ls);

        float maxpd = 1.0f / sum;      // max element has e == 1.0f exactly
        float lek = 0.f;
        float ek[4];
        #pragma unroll
        for (int r = 0; r < 4; r++) {
            float pd = e[r] / sum;
            bool keep = (pd > (1.0f / 129.0f)) || (pd == maxpd);
            ek[r] = keep ? e[r] : 0.f;
            lek += ek[r];
        }
        float sum2 = wredSum(lek);

        #pragma unroll
        for (int r = 0; r < 4; r++) {
            int m = l + 32 * r;
            float P  = ek[r] / sum2;
            float an = A[(size_t)bn * NN + m] * 0.99f + P * 0.01f;
            out[OFF_A + (size_t)bn * NN + m] = an;
            ans[w * NN + m] = an;
        }
        __syncwarp();

        const float* aw = ans + w * NN;
        #pragma unroll
        for (int r = 0; r < 2; r++) {
            int col = l + 32 * r;
            float acc = 0.f;
            #pragma unroll 8
            for (int m = 0; m < NN; m++)
                acc += aw[m] * Os[m * K2_LDK + col];
            out[OFF_T + bn * DD + col] = acc;
            float err = out[bn * DD + col] - acc;
            ae += err; ae2 += err * err;
            am += fabsf(state[bn * DD + col]);
        }
    }

    ae  = wredSum(ae);
    ae2 = wredSum(ae2);
    am  = wredSum(am);
    if (l == 0) {
        g_pbn_e[bn]  = ae;
        g_pbn_e2[bn] = ae2;
        g_pbn_m[bn]  = am;
    }

    __shared__ int isLast;
    __syncthreads();
    if (t == 0) {
        __threadfence();
        unsigned old = atomicAdd(&g_cnt, 1u);
        isLast = (old == 127u) ? 1 : 0;
    }
    __syncthreads();
    if (isLast) {
        if (t < 128) {
            int bb = t >> 3, j = t & 7;
            float s = 0.f;
            int base = bb * NN + j * 16;
            #pragma unroll
            for (int i = 0; i < 16; i++) s += g_pbn_m[base + i];
            #pragma unroll
            for (int o = 4; o; o >>= 1) s += __shfl_xor_sync(0xffffffffu, s, o);
            if (j == 0) g_mag[bb] = s;
        }
        {
            float e = 0.f, e2 = 0.f;
            for (int i = t; i < BN; i += 512) { e += g_pbn_e[i]; e2 += g_pbn_e2[i]; }
            e = wredSum(e); e2 = wredSum(e2);
            __shared__ float r0[16], r1[16];
            if (l == 0) { r0[w] = e; r1[w] = e2; }
            __syncthreads();
            if (t == 0) {
                float E = 0.f, E2 = 0.f;
                #pragma unroll
                for (int i = 0; i < 16; i++) { E += r0[i]; E2 += r1[i]; }
                const float M = (float)BND;
                float var = (E2 - E * E / M) / (M - 1.0f);
                g_std = sqrtf(fmaxf(var, 0.f));
                g_cnt = 0u;   // reset for next graph replay
            }
        }
        if (t < DD) {
            float scf    = (float)(*stepc) + 1.0f;
            float center = fmodf(scf * 0.5f, 64.0f);
            float d = fabsf((float)t - center);
            d = fminf(d, 64.f - d);
            g_gmask[t] = expf(-d * d / 0.020001f);
        }
    }
}

// ---------------------------------------------------------------------------
// K4 (PDL secondary of k2): input-array loads before sync; prediction,
// target and k2-produced stats after. Warp per (b,n), 256 blocks x 256.
// ---------------------------------------------------------------------------
__global__ void __launch_bounds__(256) k4_coef(
    const float* __restrict__ state,
    const float* __restrict__ Ebase,
    const float* __restrict__ n1raw,
    const float* __restrict__ n2raw,
    const float* __restrict__ out)
{
    int bn   = blockIdx.x * 8 + (threadIdx.x >> 5);
    int lane = threadIdx.x & 31;
    int b    = bn >> 7;
    int g0   = bn * DD + lane;
    int g1   = g0 + 32;

    // pre-sync: pure input arrays
    float Eb0A = Ebase[g0], Eb0B = Ebase[g1];
    float st0 = state[g0],  st1 = state[g1];
    float n10 = n1raw[g0],  n11 = n1raw[g1];
    float n20 = n2raw[g0],  n21 = n2raw[g1];

    cudaGridDependencySynchronize();   // k2 done => k1 done too

    float errA = out[g0] - out[OFF_T + g0];
    float errB = out[g1] - out[OFF_T + g1];

    float mx = wredMax(fmaxf(errA, errB));
    float exA = expf(errA - mx), exB = expf(errB - mx);
    float sm = wredSum(exA + exB);
    float EcA = exA / sm, EcB = exB / sm;

    float EbA = (Eb0A == 0.f) ? EcA : Eb0A;
    float EbB = (Eb0B == 0.f) ? EcB : Eb0B;
    EbA = EbA * 0.95f + 0.05f * EcA;
    EbB = EbB * 0.95f + 0.05f * EcB;
    float advA = EcA - EbA, advB = EcB - EbB;
    float plA = 1.f + advA * rsqrtf(advA * advA + 1e-6f);
    float plB = 1.f + advB * rsqrtf(advB * advB + 1e-6f);
    float mkA = (EbA > 0.f) ? 1.f : 0.f;
    float mkB = (EbB > 0.f) ? 1.f : 0.f;

    float inv_mag = 1.f / (1.f + g_mag[b]);
    float sd = g_std * 0.8f;
    float nsA = st0 + n10 * inv_mag + n20 * sd;
    float nsB = st1 + n11 * inv_mag + n21 * sd;

    float se2 = wredSum(errA * errA + errB * errB);
    float sn2 = wredSum(nsA * nsA + nsB * nsB);
    float rn = rsqrtf((se2 * (1.f / DD)) * (sn2 * (1.f / DD)) + 1e-6f);

    g_coef[g0]  = -errA * rn * plA * mkA;
    g_coef[g1]  = -errB * rn * plB * mkB;
    g_noisy[g0] = nsA;
    g_noisy[g1] = nsB;
}

// ---------------------------------------------------------------------------
// K5 (PDL secondary of k4): W loads before sync (input arrays, keeps the
// champion's reg budget); coef/noisy/gmask after. Reversed walk; __ldcs on
// M, __stcs on stores.
// ---------------------------------------------------------------------------
__device__ __forceinline__ float newW(float w, float wlat, float m, float h, float g) {
    float grad = h + 0.01f * wlat - 0.01f * w;     // LAT_DECAY*W_lat - WD*W_self
    return w + 0.0033f * (m * 0.4f + 0.6f * grad * g);
}

__global__ void __launch_bounds__(256, 7) k5_update(
    const float* __restrict__ W1, const float* __restrict__ W2, const float* __restrict__ W3,
    const float* __restrict__ M1, const float* __restrict__ M2, const float* __restrict__ M3,
    float* __restrict__ out)
{
    int t   = threadIdx.x;
    int tx  = t & 15;
    int blk = (int)gridDim.x - 1 - (int)blockIdx.x;   // reversed walk
    int row = blk * 16 + (t >> 4);         // 0..BND-1  (b,n,i)
    int bn  = row >> 6;
    size_t b4 = (size_t)row * 16 + tx;     // float4 index into (BND x D) matrices

    // pre-sync: W loads (pure inputs) fly while k4 finishes
    float4 w1 = ((const float4*)W1)[b4];
    float4 w2 = ((const float4*)W2)[b4];
    float4 w3 = ((const float4*)W3)[b4];

    cudaGridDependencySynchronize();   // wait for k4 (g_coef, g_noisy)

    float  c  = g_coef[row];
    float4 ns = ((const float4*)g_noisy)[bn * 16 + tx];
    float4 gm = ((const float4*)g_gmask)[tx];
    float4 h  = { c * ns.x, c * ns.y, c * ns.z, c * ns.w };

    // --- W1 update ---
    {
        float4 m1 = __ldcs(((const float4*)M1) + b4);
        float4 t1;
        t1.x = newW(w1.x, w3.x, m1.x, h.x, gm.x);
        t1.y = newW(w1.y, w3.y, m1.y, h.y, gm.y);
        t1.z = newW(w1.z, w3.z, m1.z, h.z, gm.z);
        t1.w = newW(w1.w, w3.w, m1.w, h.w, gm.w);
        float s1 = t1.x*t1.x + t1.y*t1.y + t1.z*t1.z + t1.w*t1.w;
        #pragma unroll
        for (int o = 8; o; o >>= 1) s1 += __shfl_xor_sync(0xffffffffu, s1, o);
        float r1 = rsqrtf(s1 * (1.f / 64.f) + 1e-6f);
        float4 o1 = { t1.x*r1, t1.y*r1, t1.z*r1, t1.w*r1 };
        __stcs(((float4*)(out + OFF_W1)) + b4, o1);
    }
    // --- W2 update ---
    {
        float4 m2 = __ldcs(((const float4*)M2) + b4);
        float4 t2;
        t2.x = newW(w2.x, w1.x, m2.x, h.x, gm.x);
        t2.y = newW(w2.y, w1.y, m2.y, h.y, gm.y);
        t2.z = newW(w2.z, w1.z, m2.z, h.z, gm.z);
        t2.w = newW(w2.w, w1.w, m2.w, h.w, gm.w);
        float s2 = t2.x*t2.x + t2.y*t2.y + t2.z*t2.z + t2.w*t2.w;
        #pragma unroll
        for (int o = 8; o; o >>= 1) s2 += __shfl_xor_sync(0xffffffffu, s2, o);
        float r2 = rsqrtf(s2 * (1.f / 64.f) + 1e-6f);
        float4 o2 = { t2.x*r2, t2.y*r2, t2.z*r2, t2.w*r2 };
        __stcs(((float4*)(out + OFF_W2)) + b4, o2);
    }
    // --- W3 update ---
    {
        float4 m3 = __ldcs(((const float4*)M3) + b4);
        float4 t3;
        t3.x = newW(w3.x, w2.x, m3.x, h.x, gm.x);
        t3.y = newW(w3.y, w2.y, m3.y, h.y, gm.y);
        t3.z = newW(w3.z, w2.z, m3.z, h.z, gm.z);
        t3.w = newW(w3.w, w2.w, m3.w, h.w, gm.w);
        float s3 = t3.x*t3.x + t3.y*t3.y + t3.z*t3.z + t3.w*t3.w;
        #pragma unroll
        for (int o = 8; o; o >>= 1) s3 += __shfl_xor_sync(0xffffffffu, s3, o);
        float r3 = rsqrtf(s3 * (1.f / 64.f) + 1e-6f);
        float4 o3 = { t3.x*r3, t3.y*r3, t3.z*r3, t3.w*r3 };
        __stcs(((float4*)(out + OFF_W3)) + b4, o3);
    }
}

// ---------------------------------------------------------------------------
extern "C" void kernel_launch(void* const* d_in, const int* in_sizes, int n_in,
                              void* d_out, int out_size)
{
    const float* eye     = (const float*)d_in[0];
    const float* stomach = (const float*)d_in[1];
    const float* state   = (const float*)d_in[2];
    const float* outputv = (const float*)d_in[3];
    const float* W1      = (const float*)d_in[4];
    const float* W2      = (const float*)d_in[5];
    const float* W3      = (const float*)d_in[6];
    const float* M1      = (const float*)d_in[7];
    const float* M2      = (const float*)d_in[8];
    const float* M3      = (const float*)d_in[9];
    const float* Ebase   = (const float*)d_in[10];
    const float* A       = (const float*)d_in[11];
    const float* noiseA  = (const float*)d_in[12];
    const float* n1raw   = (const float*)d_in[13];
    const float* n2raw   = (const float*)d_in[14];
    const int*   stepc   = (const int*)d_in[15];
    float* out = (float*)d_out;

    cudaFuncSetAttribute(k2_attn, cudaFuncAttributeMaxDynamicSharedMemorySize,
                         K2_SMEM_BYTES);

    cudaLaunchAttribute pdl[1];
    pdl[0].id = cudaLaunchAttributeProgrammaticStreamSerialization;
    pdl[0].val.programmaticStreamSerializationAllowed = 1;

    // k1: normal launch
    k1_qkp<<<BN, 192>>>(state, W1, W2, W3, out);

    // k2: PDL secondary of k1
    {
        cudaLaunchConfig_t cfg = {};
        cfg.gridDim = dim3(128);
        cfg.blockDim = dim3(512);
        cfg.dynamicSmemBytes = K2_SMEM_BYTES;
        cfg.stream = 0;
        cfg.attrs = pdl;
        cfg.numAttrs = 1;
        cudaLaunchKernelEx(&cfg, k2_attn, A, noiseA, outputv, eye, stomach,
                           state, stepc, out);
    }

    // k4: PDL secondary of k2
    {
        cudaLaunchConfig_t cfg = {};
        cfg.gridDim = dim3(BN / 8);
        cfg.blockDim = dim3(256);
        cfg.stream = 0;
        cfg.attrs = pdl;
        cfg.numAttrs = 1;
        cudaLaunchKernelEx(&cfg, k4_coef, state, Ebase, n1raw, n2raw,
                           (const float*)out);
    }

    // k5: PDL secondary of k4
    {
        cudaLaunchConfig_t cfg = {};
        cfg.gridDim = dim3(BND / 16);
        cfg.blockDim = dim3(256);
        cfg.stream = 0;
        cfg.attrs = pdl;
        cfg.numAttrs = 1;
        cudaLaunchKernelEx(&cfg, k5_update, W1, W2, W3, M1, M2, M3, out);
    }
}